// round 8
// baseline (speedup 1.0000x reference)
#include <cuda_runtime.h>
#include <cuda_bf16.h>
#include <math.h>
#include <float.h>
#include <stdint.h>

#define NN      10000
#define EREAL   200000
#define E2TOT   210000
#define BBATCH  8192

// ---------------- device scratch ----------------
__device__ float g_x0[NN*256];          // fp32 combine buffer (proj outputs + gene z0)
__device__ float g_x0b[NN*256];         // gene split-K partial (z1)
__device__ float g_xh[NN*512];
__device__ float g_feat[NN*512];
__device__ float g_alsrc[NN*4];
__device__ float g_aldst[NN*4];
__device__ int   g_cnt[NN];
__device__ float g_attrsum[NN];
__device__ float g_loop[NN];
__device__ int   g_ptr[NN+1];
__device__ int   g_cur[NN];
__device__ int   g_csrc[E2TOT];
__device__ float g_cea[E2TOT];
__device__ int   g_corig[E2TOT];
__device__ unsigned char g_cwin[E2TOT];
__device__ float g_ke[4];
__device__ int   g_f64;
__device__ int   g_src[EREAL];
__device__ int   g_dst[EREAL];
__device__ int   g_idd[BBATCH];
__device__ int   g_idc[BBATCH];

// bf16 hi/lo operand planes
__device__ __nv_bfloat16 g_geneH[81000000], g_geneL[81000000];
__device__ __nv_bfloat16 g_WgH[2304000],   g_WgL[2304000];
__device__ __nv_bfloat16 g_drugH[500*512], g_drugL[500*512];
__device__ __nv_bfloat16 g_cellH[500*512], g_cellL[500*512];
__device__ __nv_bfloat16 g_WdH[256*512],   g_WdL[256*512];
__device__ __nv_bfloat16 g_WcH[256*512],   g_WcL[256*512];
__device__ __nv_bfloat16 g_l0H[131072],    g_l0L[131072];
__device__ __nv_bfloat16 g_l1H[262144],    g_l1L[262144];
__device__ __nv_bfloat16 g_x0H[NN*256],    g_x0L[NN*256];
__device__ __nv_bfloat16 g_featH[NN*512],  g_featL[NN*512];

// ---------------- helpers ----------------
__device__ __forceinline__ float warpSum(float v){
  #pragma unroll
  for (int o=16;o;o>>=1) v += __shfl_down_sync(0xffffffffu, v, o);
  return v;
}
__device__ __forceinline__ float warpMax(float v){
  #pragma unroll
  for (int o=16;o;o>>=1) v = fmaxf(v, __shfl_down_sync(0xffffffffu, v, o));
  return v;
}

// ---------------- conversion kernels ----------------
__global__ void k_cvt2bf(const float4* __restrict__ x, uint2* __restrict__ h,
                         uint2* __restrict__ l, int n4)
{
  int i = blockIdx.x*blockDim.x + threadIdx.x;
  if (i < n4){
    float4 v = x[i];
    __nv_bfloat16 hh[4], ll[4];
    #pragma unroll
    for (int u = 0; u < 4; u++){
      float f = (&v.x)[u];
      hh[u] = __float2bfloat16(f);
      ll[u] = __float2bfloat16(f - __bfloat162float(hh[u]));
    }
    h[i] = *reinterpret_cast<uint2*>(hh);
    l[i] = *reinterpret_cast<uint2*>(ll);
  }
}

__global__ void k_cvt2bf_pad(const float* __restrict__ x, __nv_bfloat16* __restrict__ h,
                             __nv_bfloat16* __restrict__ l, int rows, int cols, int cpad)
{
  int i = blockIdx.x*blockDim.x + threadIdx.x;
  if (i < rows*cpad){
    int r = i / cpad, c = i - r*cpad;
    float v = (c < cols) ? x[r*cols + c] : 0.f;
    __nv_bfloat16 hv = __float2bfloat16(v);
    h[i] = hv;
    l[i] = __float2bfloat16(v - __bfloat162float(hv));
  }
}

__global__ void k_comb(const float* __restrict__ a, const float* __restrict__ b,
                       __nv_bfloat16* __restrict__ h, __nv_bfloat16* __restrict__ l,
                       int n, int addFrom)
{
  int i = blockIdx.x*blockDim.x + threadIdx.x;
  if (i < n){
    float v = a[i] + ((i >= addFrom) ? b[i] : 0.f);
    __nv_bfloat16 hv = __float2bfloat16(v);
    h[i] = hv;
    l[i] = __float2bfloat16(v - __bfloat162float(hv));
  }
}

// ---------------- preprocessing ----------------
__global__ void k_zero()
{
  int i = blockIdx.x*blockDim.x + threadIdx.x;
  if (i < NN){ g_cnt[i]=0; g_attrsum[i]=0.f; }
  if (i == 0) g_f64 = 1;
}

__global__ void k_detect(const long long* __restrict__ ei)
{
  int i = blockIdx.x*blockDim.x + threadIdx.x;
  if (i < EREAL){
    long long v = ei[i];
    if (v < 0 || v >= NN) g_f64 = 0;
  }
}

__global__ void k_cvt_edges_deg(const void* __restrict__ ei, const float* __restrict__ ea)
{
  int e = blockIdx.x*blockDim.x + threadIdx.x;
  if (e < EREAL){
    int s, d;
    if (g_f64){
      const long long* p = (const long long*)ei;
      s = (int)p[e]; d = (int)p[EREAL + e];
    } else {
      const int* p = (const int*)ei;
      s = p[e]; d = p[EREAL + e];
    }
    g_src[e] = s; g_dst[e] = d;
    atomicAdd(&g_cnt[d], 1);
    atomicAdd(&g_attrsum[d], ea[e]);
  }
}

__global__ void k_cvt_idx(const void* __restrict__ idd, const void* __restrict__ idc)
{
  int i = blockIdx.x*blockDim.x + threadIdx.x;
  if (i < BBATCH){
    if (g_f64){
      g_idd[i] = (int)((const long long*)idd)[i];
      g_idc[i] = (int)((const long long*)idc)[i];
    } else {
      g_idd[i] = ((const int*)idd)[i];
      g_idc[i] = ((const int*)idc)[i];
    }
  }
}

__global__ void k_loopattr()
{
  int i = blockIdx.x*blockDim.x + threadIdx.x;
  if (i < NN){
    float c = (float)g_cnt[i];
    g_loop[i] = g_attrsum[i] / fmaxf(c, 1.0f);
  }
}

__global__ void k_scan()
{
  __shared__ int s[1024];
  int tid = threadIdx.x;
  if (tid == 0) g_ptr[0] = 0;
  int offset = 0;
  for (int base = 0; base < NN; base += 1024){
    int i = base + tid;
    int v = (i < NN) ? (g_cnt[i] + 1) : 0;
    s[tid] = v; __syncthreads();
    for (int d = 1; d < 1024; d <<= 1){
      int t = (tid >= d) ? s[tid - d] : 0;
      __syncthreads();
      s[tid] += t;
      __syncthreads();
    }
    if (i < NN){
      g_ptr[i+1] = offset + s[tid];
      g_cur[i]   = offset + s[tid] - v;
    }
    int tot = s[1023];
    __syncthreads();
    offset += tot;
  }
}

__global__ void k_scatter_all(const float* __restrict__ ea)
{
  int idx = blockIdx.x*blockDim.x + threadIdx.x;
  if (idx < EREAL){
    int sI = g_src[idx], d = g_dst[idx];
    int pos = atomicAdd(&g_cur[d], 1);
    g_csrc[pos] = sI; g_cea[pos] = ea[idx]; g_corig[pos] = idx;
  } else if (idx < EREAL + NN){
    int n = idx - EREAL;
    int pos = atomicAdd(&g_cur[n], 1);
    g_csrc[pos] = n; g_cea[pos] = g_loop[n]; g_corig[pos] = EREAL + n;
  }
}

__global__ void k_winner()
{
  __shared__ int s_s[512], s_o[512];
  int n = blockIdx.x; int lane = threadIdx.x;
  int b = g_ptr[n], e = g_ptr[n+1];
  int len = e - b;
  if (len <= 512){
    for (int i = lane; i < len; i += 32){ s_s[i] = g_csrc[b+i]; s_o[i] = g_corig[b+i]; }
    __syncwarp();
    for (int i = lane; i < len; i += 32){
      int sI = s_s[i], o = s_o[i];
      unsigned char w = 1;
      for (int j = 0; j < len; j++)
        if (s_s[j] == sI && s_o[j] > o){ w = 0; break; }
      g_cwin[b+i] = w;
    }
  } else {
    for (int i = b + lane; i < e; i += 32){
      int sI = g_csrc[i]; int o = g_corig[i];
      unsigned char w = 1;
      for (int j = b; j < e; j++)
        if (g_csrc[j] == sI && g_corig[j] > o){ w = 0; break; }
      g_cwin[i] = w;
    }
  }
}

// ================= bf16 hi/lo tensor-core GEMM (cp.async pipeline) =================
// C[M,Nn] = (AH+AL)[M,K] @ (BH+BL)[Nn,K]^T (+bias); bf16 operands pre-split in gmem.
// C = Ah*Bh + Al*Bh + Ah*Bl.  BM=128 BN=256 BK=32, warp tile 64x64, 2-stage cp.async.
#define BM 128
#define BN 256
#define BK 32
#define A_PL 10240                    // 128 rows * 80B
#define B_PL 20480                    // 256 rows * 80B
#define STG  (2*A_PL + 2*B_PL)        // 61440
#define GEMM_SMEM (2*STG)             // 122880

__device__ __forceinline__ void mma_bf16(
  float& c0, float& c1, float& c2, float& c3,
  uint32_t a0, uint32_t a1, uint32_t a2, uint32_t a3,
  uint32_t b0, uint32_t b1)
{
  asm volatile(
    "mma.sync.aligned.m16n8k16.row.col.f32.bf16.bf16.f32 "
    "{%0,%1,%2,%3}, {%4,%5,%6,%7}, {%8,%9}, {%0,%1,%2,%3};"
    : "+f"(c0), "+f"(c1), "+f"(c2), "+f"(c3)
    : "r"(a0), "r"(a1), "r"(a2), "r"(a3), "r"(b0), "r"(b1));
}

#define LDSM4(d0,d1,d2,d3,addr) \
  asm volatile("ldmatrix.sync.aligned.m8n8.x4.shared.b16 {%0,%1,%2,%3}, [%4];" \
    : "=r"(d0),"=r"(d1),"=r"(d2),"=r"(d3) : "r"(addr))

__device__ __forceinline__ void cpa16(uint32_t dst, const void* src, int sz){
  asm volatile("cp.async.cg.shared.global [%0], [%1], 16, %2;"
               :: "r"(dst), "l"(src), "r"(sz) : "memory");
}

__global__ __launch_bounds__(256, 1) void k_gemm_bf(
  const __nv_bfloat16* __restrict__ AH, const __nv_bfloat16* __restrict__ AL,
  const __nv_bfloat16* __restrict__ BH, const __nv_bfloat16* __restrict__ BL,
  const float* __restrict__ bias,
  float* __restrict__ C, float* __restrict__ C2,
  int M, int K, int Nn)
{
  extern __shared__ __align__(128) char sdyn[];
  uint32_t smb = (uint32_t)__cvta_generic_to_shared(sdyn);

  int tid = threadIdx.x;
  int lane = tid & 31, wid = tid >> 5;
  int gid = lane >> 2, tig = lane & 3;
  int mbase = (wid & 1) * 64;
  int nbase = (wid >> 1) * 64;
  int bm = blockIdx.y * BM, bn = blockIdx.x * BN;

  // split-K
  int kidx = blockIdx.z, nparts = gridDim.z;
  int ksplit = ((K + nparts*BK - 1) / (nparts*BK)) * BK;
  int kbeg = kidx * ksplit;
  int kend = min(K, kbeg + ksplit);
  float* Cout = kidx ? C2 : C;
  const float* bp = (kidx == 0) ? bias : nullptr;

  // ldmatrix byte offsets within a plane
  int r8 = lane & 7, mat = lane >> 3;
  uint32_t aoff[4], boff[4];
  #pragma unroll
  for (int mt = 0; mt < 4; mt++){
    int arow = mbase + mt*16 + (mat & 1)*8 + r8;
    aoff[mt] = (uint32_t)(arow*80 + (mat >> 1)*16);
  }
  #pragma unroll
  for (int p = 0; p < 4; p++){
    int brow = nbase + p*16 + (mat >> 1)*8 + r8;
    boff[p] = (uint32_t)(brow*80 + (mat & 1)*16);
  }

  float acc[4][8][4];
  #pragma unroll
  for (int i=0;i<4;i++)
    #pragma unroll
    for (int j=0;j<8;j++)
      #pragma unroll
      for (int q=0;q<4;q++) acc[i][j][q] = 0.f;

  int tiles = (kend - kbeg + BK - 1) / BK;

  auto issue = [&](int stage, int k0){
    uint32_t st = smb + (uint32_t)(stage * STG);
    #pragma unroll
    for (int j = 0; j < 2; j++){          // A: 512 chunks, 2/thread/plane
      int chunk = tid + j*256;
      int row = chunk >> 2, col = chunk & 3;
      int grow = bm + row;
      int gk = k0 + col*8;
      int rem = kend - gk;
      int sz = (grow < M) ? min(max(rem, 0)*2, 16) : 0;
      size_t go = sz ? ((size_t)grow*K + gk) : 0;
      uint32_t d = st + (uint32_t)(row*80 + col*16);
      cpa16(d,        AH + go, sz);
      cpa16(d + A_PL, AL + go, sz);
    }
    #pragma unroll
    for (int j = 0; j < 4; j++){          // B: 1024 chunks, 4/thread/plane
      int chunk = tid + j*256;
      int row = chunk >> 2, col = chunk & 3;
      int grow = bn + row;
      int gk = k0 + col*8;
      int rem = kend - gk;
      int sz = (grow < Nn) ? min(max(rem, 0)*2, 16) : 0;
      size_t go = sz ? ((size_t)grow*K + gk) : 0;
      uint32_t d = st + (uint32_t)(2*A_PL + row*80 + col*16);
      cpa16(d,        BH + go, sz);
      cpa16(d + B_PL, BL + go, sz);
    }
    asm volatile("cp.async.commit_group;" ::: "memory");
  };

  issue(0, kbeg);

  for (int t = 0; t < tiles; t++){
    if (t + 1 < tiles){
      issue((t+1) & 1, kbeg + (t+1)*BK);
      asm volatile("cp.async.wait_group 1;" ::: "memory");
    } else {
      asm volatile("cp.async.wait_group 0;" ::: "memory");
    }
    __syncthreads();

    uint32_t st = smb + (uint32_t)((t & 1) * STG);
    uint32_t aP0 = st, aP1 = st + A_PL;
    uint32_t bP0 = st + 2*A_PL, bP1 = st + 2*A_PL + B_PL;

    #pragma unroll
    for (int kso = 0; kso < 64; kso += 32){   // two k16 steps (byte offset)
      uint32_t ah[4][4], al_[4][4], b[8][2];
      #pragma unroll
      for (int mt = 0; mt < 4; mt++)
        LDSM4(ah[mt][0], ah[mt][1], ah[mt][2], ah[mt][3], aP0 + aoff[mt] + kso);
      #pragma unroll
      for (int mt = 0; mt < 4; mt++)
        LDSM4(al_[mt][0], al_[mt][1], al_[mt][2], al_[mt][3], aP1 + aoff[mt] + kso);
      #pragma unroll
      for (int p = 0; p < 4; p++)
        LDSM4(b[2*p][0], b[2*p][1], b[2*p+1][0], b[2*p+1][1], bP0 + boff[p] + kso);
      #pragma unroll
      for (int mt = 0; mt < 4; mt++)
        #pragma unroll
        for (int nt = 0; nt < 8; nt++){
          float* c = acc[mt][nt];
          mma_bf16(c[0],c[1],c[2],c[3], ah[mt][0],ah[mt][1],ah[mt][2],ah[mt][3], b[nt][0],b[nt][1]);
        }
      #pragma unroll
      for (int mt = 0; mt < 4; mt++)
        #pragma unroll
        for (int nt = 0; nt < 8; nt++){
          float* c = acc[mt][nt];
          mma_bf16(c[0],c[1],c[2],c[3], al_[mt][0],al_[mt][1],al_[mt][2],al_[mt][3], b[nt][0],b[nt][1]);
        }
      #pragma unroll
      for (int p = 0; p < 4; p++)
        LDSM4(b[2*p][0], b[2*p][1], b[2*p+1][0], b[2*p+1][1], bP1 + boff[p] + kso);
      #pragma unroll
      for (int mt = 0; mt < 4; mt++)
        #pragma unroll
        for (int nt = 0; nt < 8; nt++){
          float* c = acc[mt][nt];
          mma_bf16(c[0],c[1],c[2],c[3], ah[mt][0],ah[mt][1],ah[mt][2],ah[mt][3], b[nt][0],b[nt][1]);
        }
    }
    __syncthreads();
  }

  #pragma unroll
  for (int mt = 0; mt < 4; mt++){
    int row0 = bm + mbase + mt*16 + gid;
    #pragma unroll
    for (int nt = 0; nt < 8; nt++){
      int col0 = bn + nbase + nt*8 + tig*2;
      float* c = acc[mt][nt];
      float b0 = bp ? bp[col0] : 0.f;
      float b1 = bp ? bp[col0+1] : 0.f;
      if (row0 < M){
        float2 v = make_float2(c[0] + b0, c[1] + b1);
        *reinterpret_cast<float2*>(Cout + (size_t)row0*Nn + col0) = v;
      }
      if (row0 + 8 < M){
        float2 v = make_float2(c[2] + b0, c[3] + b1);
        *reinterpret_cast<float2*>(Cout + (size_t)(row0+8)*Nn + col0) = v;
      }
    }
  }
}

// ---------------- per-layer small kernels ----------------
__global__ void k_ke(const float* __restrict__ ledge, const float* __restrict__ aedge)
{
  int w = threadIdx.x >> 5, lane = threadIdx.x & 31;
  float s = 0.f;
  for (int c = lane; c < 128; c += 32) s += ledge[w*128+c]*aedge[w*128+c];
  s = warpSum(s);
  if (lane == 0) g_ke[w] = s;
}

__global__ void k_al(const float* __restrict__ xh,
                     const float* __restrict__ asrc, const float* __restrict__ adst)
{
  int n = blockIdx.x; int w = threadIdx.x >> 5, lane = threadIdx.x & 31;
  const float* row = xh + (size_t)n*512 + w*128;
  float s1 = 0.f, s2 = 0.f;
  for (int c = lane; c < 128; c += 32){
    float v = row[c];
    s1 += v*asrc[w*128+c];
    s2 += v*adst[w*128+c];
  }
  s1 = warpSum(s1); s2 = warpSum(s2);
  if (lane == 0){ g_alsrc[n*4+w] = s1; g_aldst[n*4+w] = s2; }
}

// ---------------- GAT node kernel ----------------
#define CHUNK 512
__global__ __launch_bounds__(128) void k_gat(
  const float* __restrict__ xh,
  const float* __restrict__ bias,
  const float* __restrict__ lng, const float* __restrict__ lnb,
  float* __restrict__ xout, float* __restrict__ att, int layer)
{
  __shared__ float s_alpha[CHUNK*4];
  __shared__ int   s_src[CHUNK];
  __shared__ float s_red[16];
  int n = blockIdx.x, tid = threadIdx.x;
  int warp = tid >> 5, lane = tid & 31;
  int b = g_ptr[n], e = g_ptr[n+1];

  float ad0 = g_aldst[n*4+0], ad1 = g_aldst[n*4+1], ad2 = g_aldst[n*4+2], ad3 = g_aldst[n*4+3];
  float ke0 = g_ke[0], ke1 = g_ke[1], ke2 = g_ke[2], ke3 = g_ke[3];

  float mx0=-FLT_MAX, mx1=-FLT_MAX, mx2=-FLT_MAX, mx3=-FLT_MAX;
  for (int i = b + tid; i < e; i += 128){
    int sI = g_csrc[i]; float ea = g_cea[i];
    float l0 = g_alsrc[sI*4+0]+ad0+ea*ke0; l0 = l0>0.f? l0 : 0.2f*l0;
    float l1 = g_alsrc[sI*4+1]+ad1+ea*ke1; l1 = l1>0.f? l1 : 0.2f*l1;
    float l2 = g_alsrc[sI*4+2]+ad2+ea*ke2; l2 = l2>0.f? l2 : 0.2f*l2;
    float l3 = g_alsrc[sI*4+3]+ad3+ea*ke3; l3 = l3>0.f? l3 : 0.2f*l3;
    mx0=fmaxf(mx0,l0); mx1=fmaxf(mx1,l1); mx2=fmaxf(mx2,l2); mx3=fmaxf(mx3,l3);
  }
  mx0=warpMax(mx0); mx1=warpMax(mx1); mx2=warpMax(mx2); mx3=warpMax(mx3);
  if (lane==0){ s_red[warp*4+0]=mx0; s_red[warp*4+1]=mx1; s_red[warp*4+2]=mx2; s_red[warp*4+3]=mx3; }
  __syncthreads();
  float bm0 = fmaxf(fmaxf(s_red[0],s_red[4]),  fmaxf(s_red[8], s_red[12]));
  float bm1 = fmaxf(fmaxf(s_red[1],s_red[5]),  fmaxf(s_red[9], s_red[13]));
  float bm2 = fmaxf(fmaxf(s_red[2],s_red[6]),  fmaxf(s_red[10],s_red[14]));
  float bm3 = fmaxf(fmaxf(s_red[3],s_red[7]),  fmaxf(s_red[11],s_red[15]));
  __syncthreads();

  float se0=0.f, se1=0.f, se2=0.f, se3=0.f;
  for (int i = b + tid; i < e; i += 128){
    int sI = g_csrc[i]; float ea = g_cea[i];
    float l0 = g_alsrc[sI*4+0]+ad0+ea*ke0; l0 = l0>0.f? l0 : 0.2f*l0;
    float l1 = g_alsrc[sI*4+1]+ad1+ea*ke1; l1 = l1>0.f? l1 : 0.2f*l1;
    float l2 = g_alsrc[sI*4+2]+ad2+ea*ke2; l2 = l2>0.f? l2 : 0.2f*l2;
    float l3 = g_alsrc[sI*4+3]+ad3+ea*ke3; l3 = l3>0.f? l3 : 0.2f*l3;
    se0 += expf(l0-bm0); se1 += expf(l1-bm1); se2 += expf(l2-bm2); se3 += expf(l3-bm3);
  }
  se0=warpSum(se0); se1=warpSum(se1); se2=warpSum(se2); se3=warpSum(se3);
  if (lane==0){ s_red[warp*4+0]=se0; s_red[warp*4+1]=se1; s_red[warp*4+2]=se2; s_red[warp*4+3]=se3; }
  __syncthreads();
  float inv0 = 1.f/((s_red[0]+s_red[4]+s_red[8] +s_red[12])+1e-16f);
  float inv1 = 1.f/((s_red[1]+s_red[5]+s_red[9] +s_red[13])+1e-16f);
  float inv2 = 1.f/((s_red[2]+s_red[6]+s_red[10]+s_red[14])+1e-16f);
  float inv3 = 1.f/((s_red[3]+s_red[7]+s_red[11]+s_red[15])+1e-16f);
  __syncthreads();

  float acc0=0.f, acc1=0.f, acc2=0.f, acc3=0.f;
  for (int c0 = b; c0 < e; c0 += CHUNK){
    int cl = min(CHUNK, e - c0);
    for (int i = tid; i < cl; i += 128){
      int eI = c0 + i;
      int sI = g_csrc[eI]; float ea = g_cea[eI];
      float l0 = g_alsrc[sI*4+0]+ad0+ea*ke0; l0 = l0>0.f? l0 : 0.2f*l0;
      float l1 = g_alsrc[sI*4+1]+ad1+ea*ke1; l1 = l1>0.f? l1 : 0.2f*l1;
      float l2 = g_alsrc[sI*4+2]+ad2+ea*ke2; l2 = l2>0.f? l2 : 0.2f*l2;
      float l3 = g_alsrc[sI*4+3]+ad3+ea*ke3; l3 = l3>0.f? l3 : 0.2f*l3;
      float a0 = expf(l0-bm0)*inv0, a1 = expf(l1-bm1)*inv1;
      float a2 = expf(l2-bm2)*inv2, a3 = expf(l3-bm3)*inv3;
      s_alpha[i*4+0]=a0; s_alpha[i*4+1]=a1; s_alpha[i*4+2]=a2; s_alpha[i*4+3]=a3;
      s_src[i] = sI;
      if (g_cwin[eI]){
        float v = (a0+a1+a2+a3)*0.25f;
        size_t ai = (size_t)sI*NN + n;
        if (layer == 0) att[ai] = v; else att[ai] += v;
      }
    }
    __syncthreads();
    for (int i = 0; i < cl; i++){
      const float* row = xh + (size_t)s_src[i]*512;
      float a0=s_alpha[i*4+0], a1=s_alpha[i*4+1], a2=s_alpha[i*4+2], a3=s_alpha[i*4+3];
      acc0 += a0*row[tid];
      acc1 += a1*row[tid+128];
      acc2 += a2*row[tid+256];
      acc3 += a3*row[tid+384];
    }
    __syncthreads();
  }

  acc0 += bias[tid]; acc1 += bias[tid+128]; acc2 += bias[tid+256]; acc3 += bias[tid+384];
  float ps = acc0+acc1+acc2+acc3;
  ps = warpSum(ps);
  if (lane==0) s_red[warp]=ps;
  __syncthreads();
  float mu = (s_red[0]+s_red[1]+s_red[2]+s_red[3]) * (1.f/512.f);
  __syncthreads();
  float d0=acc0-mu, d1=acc1-mu, d2=acc2-mu, d3=acc3-mu;
  float pv = d0*d0+d1*d1+d2*d2+d3*d3;
  pv = warpSum(pv);
  if (lane==0) s_red[warp]=pv;
  __syncthreads();
  float var = (s_red[0]+s_red[1]+s_red[2]+s_red[3]) * (1.f/512.f);
  float rstd = rsqrtf(var + 1e-5f);
  float* orow = xout + (size_t)n*512;
  size_t fb = (size_t)n*512 + tid;
  float r0 = fmaxf(d0*rstd*lng[tid]     + lnb[tid],     0.f);
  float r1 = fmaxf(d1*rstd*lng[tid+128] + lnb[tid+128], 0.f);
  float r2 = fmaxf(d2*rstd*lng[tid+256] + lnb[tid+256], 0.f);
  float r3 = fmaxf(d3*rstd*lng[tid+384] + lnb[tid+384], 0.f);
  orow[tid] = r0; orow[tid+128] = r1; orow[tid+256] = r2; orow[tid+384] = r3;
  __nv_bfloat16 h0=__float2bfloat16(r0), h1=__float2bfloat16(r1);
  __nv_bfloat16 h2=__float2bfloat16(r2), h3=__float2bfloat16(r3);
  g_featH[fb]     = h0; g_featL[fb]     = __float2bfloat16(r0 - __bfloat162float(h0));
  g_featH[fb+128] = h1; g_featL[fb+128] = __float2bfloat16(r1 - __bfloat162float(h1));
  g_featH[fb+256] = h2; g_featL[fb+256] = __float2bfloat16(r2 - __bfloat162float(h2));
  g_featH[fb+384] = h3; g_featL[fb+384] = __float2bfloat16(r3 - __bfloat162float(h3));
}

// ---------------- final MLP ----------------
__global__ __launch_bounds__(128) void k_mlp(
  const float* __restrict__ w, const float* __restrict__ bptr, float* __restrict__ pred)
{
  __shared__ float s_red[4];
  int bI = blockIdx.x, tid = threadIdx.x;
  const float* xd = g_feat + (size_t)g_idd[bI]*512;
  const float* xc = g_feat + (size_t)g_idc[bI]*512;
  float s = 0.f;
  for (int j = tid; j < 512; j += 128) s += xd[j]*w[j] + xc[j]*w[512+j];
  s = warpSum(s);
  if ((tid & 31) == 0) s_red[tid>>5] = s;
  __syncthreads();
  if (tid == 0) pred[bI] = s_red[0]+s_red[1]+s_red[2]+s_red[3] + bptr[0];
}

// ---------------- host ----------------
struct BfPtrs { __nv_bfloat16 *geneH,*geneL,*WgH,*WgL,*drugH,*drugL,*cellH,*cellL,
                *WdH,*WdL,*WcH,*WcL,*l0H,*l0L,*l1H,*l1L,*x0H,*x0L,*featH,*featL; };

static void launch_gemm(const __nv_bfloat16* AH, const __nv_bfloat16* AL,
                        const __nv_bfloat16* BH, const __nv_bfloat16* BL,
                        const float* bias, float* C, float* C2,
                        int M, int K, int Nn, int parts)
{
  dim3 grid((Nn + BN - 1)/BN, (M + BM - 1)/BM, parts);
  k_gemm_bf<<<grid, 256, GEMM_SMEM>>>(AH, AL, BH, BL, bias, C, C2, M, K, Nn);
}

extern "C" void kernel_launch(void* const* d_in, const int* in_sizes, int n_in,
                              void* d_out, int out_size)
{
  static bool attr_set = false;
  if (!attr_set){
    cudaFuncSetAttribute(k_gemm_bf, cudaFuncAttributeMaxDynamicSharedMemorySize,
                         GEMM_SMEM);
    attr_set = true;
  }

  bool used[64];
  for (int i = 0; i < 64; i++) used[i] = false;
  auto find = [&](int sz) -> int {
    for (int i = 0; i < n_in; i++)
      if (!used[i] && in_sizes[i] == sz){ used[i] = true; return i; }
    return -1;
  };
  int i_drug = find(250000),  i_cell = find(250000), i_gene = find(81000000);
  int i_ei   = find(400000),  i_ea   = find(200000);
  int i_idd  = find(8192),    i_idc  = find(8192);
  int i_Wd   = find(128000),  i_Wc   = find(128000), i_Wg = find(2304000);
  int i_bd   = find(256),     i_bc   = find(256),    i_bg = find(256);
  int i_l0lin = find(131072), i_l1lin = find(262144);
  int i_l0asrc=find(512), i_l0adst=find(512), i_l0ledge=find(512), i_l0aedge=find(512);
  int i_l0bias=find(512), i_l0lng=find(512),  i_l0lnb=find(512);
  int i_l1asrc=find(512), i_l1adst=find(512), i_l1ledge=find(512), i_l1aedge=find(512);
  int i_l1bias=find(512), i_l1lng=find(512),  i_l1lnb=find(512);
  int i_mw = find(1024), i_mb = find(1);
  if (i_gene < 0 || i_ei < 0 || i_mw < 0 || i_mb < 0){
    cudaMemsetAsync(d_out, 0, (size_t)out_size * sizeof(float));
    return;
  }

  const float* drug = (const float*)d_in[i_drug];
  const float* cell = (const float*)d_in[i_cell];
  const float* gene = (const float*)d_in[i_gene];
  const void*  ei   = d_in[i_ei];
  const float* ea   = (const float*)d_in[i_ea];
  const void*  idd  = d_in[i_idd];
  const void*  idc  = d_in[i_idc];
  const float* Wd = (const float*)d_in[i_Wd]; const float* bd = (const float*)d_in[i_bd];
  const float* Wc = (const float*)d_in[i_Wc]; const float* bc = (const float*)d_in[i_bc];
  const float* Wg = (const float*)d_in[i_Wg]; const float* bg = (const float*)d_in[i_bg];
  const float* l0lin = (const float*)d_in[i_l0lin];
  const float* l0asrc = (const float*)d_in[i_l0asrc]; const float* l0adst = (const float*)d_in[i_l0adst];
  const float* l0ledge = (const float*)d_in[i_l0ledge]; const float* l0aedge = (const float*)d_in[i_l0aedge];
  const float* l0bias = (const float*)d_in[i_l0bias];
  const float* l0lng = (const float*)d_in[i_l0lng]; const float* l0lnb = (const float*)d_in[i_l0lnb];
  const float* l1lin = (const float*)d_in[i_l1lin];
  const float* l1asrc = (const float*)d_in[i_l1asrc]; const float* l1adst = (const float*)d_in[i_l1adst];
  const float* l1ledge = (const float*)d_in[i_l1ledge]; const float* l1aedge = (const float*)d_in[i_l1aedge];
  const float* l1bias = (const float*)d_in[i_l1bias];
  const float* l1lng = (const float*)d_in[i_l1lng]; const float* l1lnb = (const float*)d_in[i_l1lnb];
  const float* mw = (const float*)d_in[i_mw]; const float* mb = (const float*)d_in[i_mb];

  float* pred = (float*)d_out;
  float* att  = pred + (out_size - (size_t)NN*NN);

  float *x0f, *x0b, *xh, *feat;
  cudaGetSymbolAddress((void**)&x0f,  g_x0);
  cudaGetSymbolAddress((void**)&x0b,  g_x0b);
  cudaGetSymbolAddress((void**)&xh,   g_xh);
  cudaGetSymbolAddress((void**)&feat, g_feat);

  BfPtrs P;
  cudaGetSymbolAddress((void**)&P.geneH, g_geneH); cudaGetSymbolAddress((void**)&P.geneL, g_geneL);
  cudaGetSymbolAddress((void**)&P.WgH,   g_WgH);   cudaGetSymbolAddress((void**)&P.WgL,   g_WgL);
  cudaGetSymbolAddress((void**)&P.drugH, g_drugH); cudaGetSymbolAddress((void**)&P.drugL, g_drugL);
  cudaGetSymbolAddress((void**)&P.cellH, g_cellH); cudaGetSymbolAddress((void**)&P.cellL, g_cellL);
  cudaGetSymbolAddress((void**)&P.WdH,   g_WdH);   cudaGetSymbolAddress((void**)&P.WdL,   g_WdL);
  cudaGetSymbolAddress((void**)&P.WcH,   g_WcH);   cudaGetSymbolAddress((void**)&P.WcL,   g_WcL);
  cudaGetSymbolAddress((void**)&P.l0H,   g_l0H);   cudaGetSymbolAddress((void**)&P.l0L,   g_l0L);
  cudaGetSymbolAddress((void**)&P.l1H,   g_l1H);   cudaGetSymbolAddress((void**)&P.l1L,   g_l1L);
  cudaGetSymbolAddress((void**)&P.x0H,   g_x0H);   cudaGetSymbolAddress((void**)&P.x0L,   g_x0L);
  cudaGetSymbolAddress((void**)&P.featH, g_featH); cudaGetSymbolAddress((void**)&P.featL, g_featL);

  // 1-5: order keeps the gene GEMM in the ncu-captured slot
  cudaMemsetAsync(d_out, 0, (size_t)out_size * sizeof(float));                 // 1
  k_cvt2bf<<<(81000000/4+255)/256, 256>>>((const float4*)gene,
            (uint2*)P.geneH, (uint2*)P.geneL, 81000000/4);                     // 2
  k_cvt2bf<<<(2304000/4+255)/256, 256>>>((const float4*)Wg,
            (uint2*)P.WgH, (uint2*)P.WgL, 2304000/4);                          // 3
  k_zero<<<(NN+255)/256, 256>>>();                                             // 4
  launch_gemm(P.geneH, P.geneL, P.WgH, P.WgL, bg,
              x0f + 1000*256, x0b + 1000*256, 9000, 9000, 256, 2);             // 5 <- profiled

  k_detect<<<(EREAL+255)/256, 256>>>((const long long*)ei);
  k_cvt_edges_deg<<<(EREAL+255)/256, 256>>>(ei, ea);

  // padded conversions (K=500 -> 512) + projections
  k_cvt2bf_pad<<<(500*512+255)/256, 256>>>(drug, P.drugH, P.drugL, 500, 500, 512);
  k_cvt2bf_pad<<<(500*512+255)/256, 256>>>(cell, P.cellH, P.cellL, 500, 500, 512);
  k_cvt2bf_pad<<<(256*512+255)/256, 256>>>(Wd, P.WdH, P.WdL, 256, 500, 512);
  k_cvt2bf_pad<<<(256*512+255)/256, 256>>>(Wc, P.WcH, P.WcL, 256, 500, 512);
  launch_gemm(P.drugH, P.drugL, P.WdH, P.WdL, bd, x0f,           nullptr, 500, 512, 256, 1);
  launch_gemm(P.cellH, P.cellL, P.WcH, P.WcL, bc, x0f + 500*256, nullptr, 500, 512, 256, 1);

  // combine split-K partials -> x0 hi/lo
  k_comb<<<(NN*256+255)/256, 256>>>(x0f, x0b, P.x0H, P.x0L, NN*256, 1000*256);

  // layer weights -> hi/lo
  k_cvt2bf<<<(131072/4+255)/256, 256>>>((const float4*)l0lin,
            (uint2*)P.l0H, (uint2*)P.l0L, 131072/4);
  k_cvt2bf<<<(262144/4+255)/256, 256>>>((const float4*)l1lin,
            (uint2*)P.l1H, (uint2*)P.l1L, 262144/4);

  k_cvt_idx<<<(BBATCH+255)/256, 256>>>(idd, idc);
  k_loopattr<<<(NN+255)/256, 256>>>();
  k_scan<<<1, 1024>>>();
  k_scatter_all<<<(EREAL+NN+255)/256, 256>>>(ea);
  k_winner<<<NN, 32>>>();

  // GAT layer 0
  launch_gemm(P.x0H, P.x0L, P.l0H, P.l0L, nullptr, xh, nullptr, NN, 256, 512, 1);
  k_ke<<<1, 128>>>(l0ledge, l0aedge);
  k_al<<<NN, 128>>>(xh, l0asrc, l0adst);
  k_gat<<<NN, 128>>>(xh, l0bias, l0lng, l0lnb, feat, att, 0);

  // GAT layer 1
  launch_gemm(P.featH, P.featL, P.l1H, P.l1L, nullptr, xh, nullptr, NN, 512, 512, 1);
  k_ke<<<1, 128>>>(l1ledge, l1aedge);
  k_al<<<NN, 128>>>(xh, l1asrc, l1adst);
  k_gat<<<NN, 128>>>(xh, l1bias, l1lng, l1lnb, feat, att, 1);

  k_mlp<<<8192, 128>>>(mw, mb, pred);
}

// round 9
// speedup vs baseline: 1.7804x; 1.7804x over previous
#include <cuda_runtime.h>
#include <cuda_bf16.h>
#include <math.h>
#include <float.h>
#include <stdint.h>

#define NN      10000
#define EREAL   200000
#define E2TOT   210000
#define BBATCH  8192

// ---------------- device scratch ----------------
__device__ float g_x0[NN*256];
__device__ float g_xh[NN*512];
__device__ float g_feat[NN*512];
__device__ float g_alsrc[NN*4];
__device__ float g_aldst[NN*4];
__device__ int   g_cnt[NN];
__device__ float g_attrsum[NN];
__device__ float g_loop[NN];
__device__ int   g_ptr[NN+1];
__device__ int   g_cur[NN];
__device__ int   g_csrc[E2TOT];
__device__ float g_cea[E2TOT];
__device__ int   g_corig[E2TOT];
__device__ unsigned char g_cwin[E2TOT];
__device__ float g_ke[4];
__device__ int   g_f64;
__device__ int   g_src[EREAL];
__device__ int   g_dst[EREAL];
__device__ int   g_idd[BBATCH];
__device__ int   g_idc[BBATCH];

// ---------------- helpers ----------------
__device__ __forceinline__ float warpSum(float v){
  #pragma unroll
  for (int o=16;o;o>>=1) v += __shfl_down_sync(0xffffffffu, v, o);
  return v;
}
__device__ __forceinline__ float warpMax(float v){
  #pragma unroll
  for (int o=16;o;o>>=1) v = fmaxf(v, __shfl_down_sync(0xffffffffu, v, o));
  return v;
}

// ---------------- preprocessing ----------------
__global__ void k_zero()
{
  int i = blockIdx.x*blockDim.x + threadIdx.x;
  if (i < NN){ g_cnt[i]=0; g_attrsum[i]=0.f; }
  if (i == 0) g_f64 = 1;
}

__global__ void k_detect(const long long* __restrict__ ei)
{
  int i = blockIdx.x*blockDim.x + threadIdx.x;
  if (i < EREAL){
    long long v = ei[i];
    if (v < 0 || v >= NN) g_f64 = 0;
  }
}

__global__ void k_cvt_edges_deg(const void* __restrict__ ei, const float* __restrict__ ea)
{
  int e = blockIdx.x*blockDim.x + threadIdx.x;
  if (e < EREAL){
    int s, d;
    if (g_f64){
      const long long* p = (const long long*)ei;
      s = (int)p[e]; d = (int)p[EREAL + e];
    } else {
      const int* p = (const int*)ei;
      s = p[e]; d = p[EREAL + e];
    }
    g_src[e] = s; g_dst[e] = d;
    atomicAdd(&g_cnt[d], 1);
    atomicAdd(&g_attrsum[d], ea[e]);
  }
}

__global__ void k_cvt_idx(const void* __restrict__ idd, const void* __restrict__ idc)
{
  int i = blockIdx.x*blockDim.x + threadIdx.x;
  if (i < BBATCH){
    if (g_f64){
      g_idd[i] = (int)((const long long*)idd)[i];
      g_idc[i] = (int)((const long long*)idc)[i];
    } else {
      g_idd[i] = ((const int*)idd)[i];
      g_idc[i] = ((const int*)idc)[i];
    }
  }
}

__global__ void k_loopattr()
{
  int i = blockIdx.x*blockDim.x + threadIdx.x;
  if (i < NN){
    float c = (float)g_cnt[i];
    g_loop[i] = g_attrsum[i] / fmaxf(c, 1.0f);
  }
}

__global__ void k_scan()
{
  __shared__ int s[1024];
  int tid = threadIdx.x;
  if (tid == 0) g_ptr[0] = 0;
  int offset = 0;
  for (int base = 0; base < NN; base += 1024){
    int i = base + tid;
    int v = (i < NN) ? (g_cnt[i] + 1) : 0;
    s[tid] = v; __syncthreads();
    for (int d = 1; d < 1024; d <<= 1){
      int t = (tid >= d) ? s[tid - d] : 0;
      __syncthreads();
      s[tid] += t;
      __syncthreads();
    }
    if (i < NN){
      g_ptr[i+1] = offset + s[tid];
      g_cur[i]   = offset + s[tid] - v;
    }
    int tot = s[1023];
    __syncthreads();
    offset += tot;
  }
}

__global__ void k_scatter_all(const float* __restrict__ ea)
{
  int idx = blockIdx.x*blockDim.x + threadIdx.x;
  if (idx < EREAL){
    int sI = g_src[idx], d = g_dst[idx];
    int pos = atomicAdd(&g_cur[d], 1);
    g_csrc[pos] = sI; g_cea[pos] = ea[idx]; g_corig[pos] = idx;
  } else if (idx < EREAL + NN){
    int n = idx - EREAL;
    int pos = atomicAdd(&g_cur[n], 1);
    g_csrc[pos] = n; g_cea[pos] = g_loop[n]; g_corig[pos] = EREAL + n;
  }
}

__global__ void k_winner()
{
  __shared__ int s_s[512], s_o[512];
  int n = blockIdx.x; int lane = threadIdx.x;
  int b = g_ptr[n], e = g_ptr[n+1];
  int len = e - b;
  if (len <= 512){
    for (int i = lane; i < len; i += 32){ s_s[i] = g_csrc[b+i]; s_o[i] = g_corig[b+i]; }
    __syncwarp();
    for (int i = lane; i < len; i += 32){
      int sI = s_s[i], o = s_o[i];
      unsigned char w = 1;
      for (int j = 0; j < len; j++)
        if (s_s[j] == sI && s_o[j] > o){ w = 0; break; }
      g_cwin[b+i] = w;
    }
  } else {
    for (int i = b + lane; i < e; i += 32){
      int sI = g_csrc[i]; int o = g_corig[i];
      unsigned char w = 1;
      for (int j = b; j < e; j++)
        if (g_csrc[j] == sI && g_corig[j] > o){ w = 0; break; }
      g_cwin[i] = w;
    }
  }
}

// ================= bf16 split-precision tensor-core GEMM =================
// C[M,Nn] = A[M,K] @ B[Nn,K]^T (+bias); fp32 in/out.
// x = hi + lo; C = Ah*Bh + Ah*Bl + Al*Bh.  Double-buffered smem pipeline.
#define BM 128
#define BN 128
#define BK 32
#define LDA 40                      // bf16 per row (80B)
#define ASZ (BM*LDA/2)              // u32 words per plane (2560)
#define STAGE_U32 (4*ASZ)           // Ah,Al,Bh,Bl per stage
#define STAGE_BYTES (STAGE_U32*4)   // 40960
#define SMEM_TOTAL_GEMM (2*STAGE_BYTES)  // 81920

__device__ __forceinline__ void mma_bf16(
  float& c0, float& c1, float& c2, float& c3,
  uint32_t a0, uint32_t a1, uint32_t a2, uint32_t a3,
  uint32_t b0, uint32_t b1)
{
  asm volatile(
    "mma.sync.aligned.m16n8k16.row.col.f32.bf16.bf16.f32 "
    "{%0,%1,%2,%3}, {%4,%5,%6,%7}, {%8,%9}, {%0,%1,%2,%3};"
    : "+f"(c0), "+f"(c1), "+f"(c2), "+f"(c3)
    : "r"(a0), "r"(a1), "r"(a2), "r"(a3), "r"(b0), "r"(b1));
}

#define LDSM4(d0,d1,d2,d3,addr) \
  asm volatile("ldmatrix.sync.aligned.m8n8.x4.shared.b16 {%0,%1,%2,%3}, [%4];" \
    : "=r"(d0),"=r"(d1),"=r"(d2),"=r"(d3) : "r"(addr))

__device__ __forceinline__ uint32_t pack_hi(float x, float y){
  __nv_bfloat162 h = __floats2bfloat162_rn(x, y);
  return *reinterpret_cast<uint32_t*>(&h);
}
__device__ __forceinline__ uint32_t pack_lo(float x, float y){
  float hx = __bfloat162float(__float2bfloat16(x));
  float hy = __bfloat162float(__float2bfloat16(y));
  __nv_bfloat162 l = __floats2bfloat162_rn(x - hx, y - hy);
  return *reinterpret_cast<uint32_t*>(&l);
}

__global__ __launch_bounds__(256, 1) void k_gemm_mma(
  const float* __restrict__ A, const float* __restrict__ B,
  const float* __restrict__ bias, float* __restrict__ C,
  int M, int K, int Nn)
{
  extern __shared__ __align__(16) uint32_t sdy[];   // [stage][Ah|Al|Bh|Bl]

  int tid = threadIdx.x;
  int lane = tid & 31, wid = tid >> 5;
  int gid = lane >> 2, tig = lane & 3;
  int mbase = (wid & 1) * 64;
  int nbase = (wid >> 1) * 32;
  int bm = blockIdx.y * BM, bn = blockIdx.x * BN;

  // ldmatrix byte-offsets relative to plane start
  int r8 = lane & 7, mat = lane >> 3;
  uint32_t smbase = (uint32_t)__cvta_generic_to_shared(sdy);
  uint32_t aoff[4], boff[2];
  #pragma unroll
  for (int mt = 0; mt < 4; mt++){
    int arow = mbase + mt*16 + (mat & 1)*8 + r8;
    aoff[mt] = (uint32_t)((arow*LDA + (mat >> 1)*8) * 2);
  }
  #pragma unroll
  for (int p = 0; p < 2; p++){
    int brow = nbase + p*16 + (mat >> 1)*8 + r8;
    boff[p] = (uint32_t)((brow*LDA + (mat & 1)*8) * 2);
  }

  float acc[4][4][4];
  #pragma unroll
  for (int i=0;i<4;i++)
    #pragma unroll
    for (int j=0;j<4;j++)
      #pragma unroll
      for (int q=0;q<4;q++) acc[i][j][q] = 0.f;

  float4 ra[4], rb[4];
  int tiles = (K + BK - 1) / BK;

  auto loadG = [&](const float* __restrict__ P, int rows, int rowbase, int k0, float4* r){
    #pragma unroll
    for (int i = 0; i < 4; i++){
      int f = tid + i*256;
      int rr = f >> 3, cc = (f & 7) << 2;
      int gk = k0 + cc;
      float4 v = make_float4(0.f,0.f,0.f,0.f);
      int grow = rowbase + rr;
      if (grow < rows){
        const float* base = P + (size_t)grow*K + gk;
        if (gk + 3 < K) v = *reinterpret_cast<const float4*>(base);
        else {
          float t[4];
          #pragma unroll
          for (int u=0;u<4;u++) t[u] = (gk+u < K) ? base[u] : 0.f;
          v = make_float4(t[0],t[1],t[2],t[3]);
        }
      }
      r[i] = v;
    }
  };

  auto storeS = [&](int stage){
    uint32_t* Ah = sdy + stage*STAGE_U32;
    uint32_t* Al = Ah + ASZ;
    uint32_t* Bh = Al + ASZ;
    uint32_t* Bl = Bh + ASZ;
    #pragma unroll
    for (int i = 0; i < 4; i++){
      int f = tid + i*256;
      int rr = f >> 3, cc = (f & 7) << 2;
      int idx = (rr*LDA + cc) >> 1;
      float4 v = ra[i];
      Ah[idx]   = pack_hi(v.x, v.y);
      Ah[idx+1] = pack_hi(v.z, v.w);
      Al[idx]   = pack_lo(v.x, v.y);
      Al[idx+1] = pack_lo(v.z, v.w);
      float4 w = rb[i];
      Bh[idx]   = pack_hi(w.x, w.y);
      Bh[idx+1] = pack_hi(w.z, w.w);
      Bl[idx]   = pack_lo(w.x, w.y);
      Bl[idx+1] = pack_lo(w.z, w.w);
    }
  };

  loadG(A, M, bm, 0, ra);
  loadG(B, Nn, bn, 0, rb);
  storeS(0);
  __syncthreads();

  for (int t = 0; t < tiles; t++){
    bool more = (t + 1 < tiles);
    if (more){
      loadG(A, M, bm, (t+1)*BK, ra);
      loadG(B, Nn, bn, (t+1)*BK, rb);
    }
    uint32_t stg = smbase + (uint32_t)((t & 1) * STAGE_BYTES);
    uint32_t aP0 = stg, aP1 = stg + ASZ*4;
    uint32_t bP0 = stg + 2*ASZ*4, bP1 = stg + 3*ASZ*4;
    #pragma unroll
    for (int ks = 0; ks < BK; ks += 16){
      uint32_t ah[4][4], al[4][4], bh[4][2], bl[4][2];
      #pragma unroll
      for (int mt = 0; mt < 4; mt++){
        LDSM4(ah[mt][0], ah[mt][1], ah[mt][2], ah[mt][3], aP0 + aoff[mt] + ks*2);
        LDSM4(al[mt][0], al[mt][1], al[mt][2], al[mt][3], aP1 + aoff[mt] + ks*2);
      }
      #pragma unroll
      for (int p = 0; p < 2; p++){
        LDSM4(bh[2*p][0], bh[2*p][1], bh[2*p+1][0], bh[2*p+1][1], bP0 + boff[p] + ks*2);
        LDSM4(bl[2*p][0], bl[2*p][1], bl[2*p+1][0], bl[2*p+1][1], bP1 + boff[p] + ks*2);
      }
      #pragma unroll
      for (int mt = 0; mt < 4; mt++)
        #pragma unroll
        for (int nt = 0; nt < 4; nt++){
          float* c = acc[mt][nt];
          mma_bf16(c[0],c[1],c[2],c[3], ah[mt][0],ah[mt][1],ah[mt][2],ah[mt][3], bh[nt][0],bh[nt][1]);
          mma_bf16(c[0],c[1],c[2],c[3], ah[mt][0],ah[mt][1],ah[mt][2],ah[mt][3], bl[nt][0],bl[nt][1]);
          mma_bf16(c[0],c[1],c[2],c[3], al[mt][0],al[mt][1],al[mt][2],al[mt][3], bh[nt][0],bh[nt][1]);
        }
    }
    if (more) storeS((t+1) & 1);
    __syncthreads();
  }

  #pragma unroll
  for (int mt = 0; mt < 4; mt++){
    int row0 = bm + mbase + mt*16 + gid;
    #pragma unroll
    for (int nt = 0; nt < 4; nt++){
      int col0 = bn + nbase + nt*8 + tig*2;
      float* c = acc[mt][nt];
      float b0 = bias ? bias[col0] : 0.f;
      float b1 = bias ? bias[col0+1] : 0.f;
      if (row0 < M){
        float2 v = make_float2(c[0] + b0, c[1] + b1);
        *reinterpret_cast<float2*>(C + (size_t)row0*Nn + col0) = v;
      }
      if (row0 + 8 < M){
        float2 v = make_float2(c[2] + b0, c[3] + b1);
        *reinterpret_cast<float2*>(C + (size_t)(row0+8)*Nn + col0) = v;
      }
    }
  }
}

// ---------------- per-layer small kernels ----------------
__global__ void k_ke(const float* __restrict__ ledge, const float* __restrict__ aedge)
{
  int w = threadIdx.x >> 5, lane = threadIdx.x & 31;
  float s = 0.f;
  for (int c = lane; c < 128; c += 32) s += ledge[w*128+c]*aedge[w*128+c];
  s = warpSum(s);
  if (lane == 0) g_ke[w] = s;
}

__global__ void k_al(const float* __restrict__ xh,
                     const float* __restrict__ asrc, const float* __restrict__ adst)
{
  int n = blockIdx.x; int w = threadIdx.x >> 5, lane = threadIdx.x & 31;
  const float* row = xh + (size_t)n*512 + w*128;
  float s1 = 0.f, s2 = 0.f;
  for (int c = lane; c < 128; c += 32){
    float v = row[c];
    s1 += v*asrc[w*128+c];
    s2 += v*adst[w*128+c];
  }
  s1 = warpSum(s1); s2 = warpSum(s2);
  if (lane == 0){ g_alsrc[n*4+w] = s1; g_aldst[n*4+w] = s2; }
}

// ---------------- GAT node kernel ----------------
#define CHUNK 512
__global__ __launch_bounds__(128) void k_gat(
  const float* __restrict__ xh,
  const float* __restrict__ bias,
  const float* __restrict__ lng, const float* __restrict__ lnb,
  float* __restrict__ xout, float* __restrict__ att, int layer)
{
  __shared__ float s_alpha[CHUNK*4];
  __shared__ int   s_src[CHUNK];
  __shared__ float s_red[16];
  int n = blockIdx.x, tid = threadIdx.x;
  int warp = tid >> 5, lane = tid & 31;
  int b = g_ptr[n], e = g_ptr[n+1];

  float ad0 = g_aldst[n*4+0], ad1 = g_aldst[n*4+1], ad2 = g_aldst[n*4+2], ad3 = g_aldst[n*4+3];
  float ke0 = g_ke[0], ke1 = g_ke[1], ke2 = g_ke[2], ke3 = g_ke[3];

  float mx0=-FLT_MAX, mx1=-FLT_MAX, mx2=-FLT_MAX, mx3=-FLT_MAX;
  for (int i = b + tid; i < e; i += 128){
    int sI = g_csrc[i]; float ea = g_cea[i];
    float l0 = g_alsrc[sI*4+0]+ad0+ea*ke0; l0 = l0>0.f? l0 : 0.2f*l0;
    float l1 = g_alsrc[sI*4+1]+ad1+ea*ke1; l1 = l1>0.f? l1 : 0.2f*l1;
    float l2 = g_alsrc[sI*4+2]+ad2+ea*ke2; l2 = l2>0.f? l2 : 0.2f*l2;
    float l3 = g_alsrc[sI*4+3]+ad3+ea*ke3; l3 = l3>0.f? l3 : 0.2f*l3;
    mx0=fmaxf(mx0,l0); mx1=fmaxf(mx1,l1); mx2=fmaxf(mx2,l2); mx3=fmaxf(mx3,l3);
  }
  mx0=warpMax(mx0); mx1=warpMax(mx1); mx2=warpMax(mx2); mx3=warpMax(mx3);
  if (lane==0){ s_red[warp*4+0]=mx0; s_red[warp*4+1]=mx1; s_red[warp*4+2]=mx2; s_red[warp*4+3]=mx3; }
  __syncthreads();
  float bm0 = fmaxf(fmaxf(s_red[0],s_red[4]),  fmaxf(s_red[8], s_red[12]));
  float bm1 = fmaxf(fmaxf(s_red[1],s_red[5]),  fmaxf(s_red[9], s_red[13]));
  float bm2 = fmaxf(fmaxf(s_red[2],s_red[6]),  fmaxf(s_red[10],s_red[14]));
  float bm3 = fmaxf(fmaxf(s_red[3],s_red[7]),  fmaxf(s_red[11],s_red[15]));
  __syncthreads();

  float se0=0.f, se1=0.f, se2=0.f, se3=0.f;
  for (int i = b + tid; i < e; i += 128){
    int sI = g_csrc[i]; float ea = g_cea[i];
    float l0 = g_alsrc[sI*4+0]+ad0+ea*ke0; l0 = l0>0.f? l0 : 0.2f*l0;
    float l1 = g_alsrc[sI*4+1]+ad1+ea*ke1; l1 = l1>0.f? l1 : 0.2f*l1;
    float l2 = g_alsrc[sI*4+2]+ad2+ea*ke2; l2 = l2>0.f? l2 : 0.2f*l2;
    float l3 = g_alsrc[sI*4+3]+ad3+ea*ke3; l3 = l3>0.f? l3 : 0.2f*l3;
    se0 += expf(l0-bm0); se1 += expf(l1-bm1); se2 += expf(l2-bm2); se3 += expf(l3-bm3);
  }
  se0=warpSum(se0); se1=warpSum(se1); se2=warpSum(se2); se3=warpSum(se3);
  if (lane==0){ s_red[warp*4+0]=se0; s_red[warp*4+1]=se1; s_red[warp*4+2]=se2; s_red[warp*4+3]=se3; }
  __syncthreads();
  float inv0 = 1.f/((s_red[0]+s_red[4]+s_red[8] +s_red[12])+1e-16f);
  float inv1 = 1.f/((s_red[1]+s_red[5]+s_red[9] +s_red[13])+1e-16f);
  float inv2 = 1.f/((s_red[2]+s_red[6]+s_red[10]+s_red[14])+1e-16f);
  float inv3 = 1.f/((s_red[3]+s_red[7]+s_red[11]+s_red[15])+1e-16f);
  __syncthreads();

  float acc0=0.f, acc1=0.f, acc2=0.f, acc3=0.f;
  for (int c0 = b; c0 < e; c0 += CHUNK){
    int cl = min(CHUNK, e - c0);
    for (int i = tid; i < cl; i += 128){
      int eI = c0 + i;
      int sI = g_csrc[eI]; float ea = g_cea[eI];
      float l0 = g_alsrc[sI*4+0]+ad0+ea*ke0; l0 = l0>0.f? l0 : 0.2f*l0;
      float l1 = g_alsrc[sI*4+1]+ad1+ea*ke1; l1 = l1>0.f? l1 : 0.2f*l1;
      float l2 = g_alsrc[sI*4+2]+ad2+ea*ke2; l2 = l2>0.f? l2 : 0.2f*l2;
      float l3 = g_alsrc[sI*4+3]+ad3+ea*ke3; l3 = l3>0.f? l3 : 0.2f*l3;
      float a0 = expf(l0-bm0)*inv0, a1 = expf(l1-bm1)*inv1;
      float a2 = expf(l2-bm2)*inv2, a3 = expf(l3-bm3)*inv3;
      s_alpha[i*4+0]=a0; s_alpha[i*4+1]=a1; s_alpha[i*4+2]=a2; s_alpha[i*4+3]=a3;
      s_src[i] = sI;
      if (g_cwin[eI]){
        float v = (a0+a1+a2+a3)*0.25f;
        size_t ai = (size_t)sI*NN + n;
        if (layer == 0) att[ai] = v; else att[ai] += v;
      }
    }
    __syncthreads();
    for (int i = 0; i < cl; i++){
      const float* row = xh + (size_t)s_src[i]*512;
      float a0=s_alpha[i*4+0], a1=s_alpha[i*4+1], a2=s_alpha[i*4+2], a3=s_alpha[i*4+3];
      acc0 += a0*row[tid];
      acc1 += a1*row[tid+128];
      acc2 += a2*row[tid+256];
      acc3 += a3*row[tid+384];
    }
    __syncthreads();
  }

  acc0 += bias[tid]; acc1 += bias[tid+128]; acc2 += bias[tid+256]; acc3 += bias[tid+384];
  float ps = acc0+acc1+acc2+acc3;
  ps = warpSum(ps);
  if (lane==0) s_red[warp]=ps;
  __syncthreads();
  float mu = (s_red[0]+s_red[1]+s_red[2]+s_red[3]) * (1.f/512.f);
  __syncthreads();
  float d0=acc0-mu, d1=acc1-mu, d2=acc2-mu, d3=acc3-mu;
  float pv = d0*d0+d1*d1+d2*d2+d3*d3;
  pv = warpSum(pv);
  if (lane==0) s_red[warp]=pv;
  __syncthreads();
  float var = (s_red[0]+s_red[1]+s_red[2]+s_red[3]) * (1.f/512.f);
  float rstd = rsqrtf(var + 1e-5f);
  float* orow = xout + (size_t)n*512;
  float y0 = d0*rstd*lng[tid]     + lnb[tid];     orow[tid]     = fmaxf(y0, 0.f);
  float y1 = d1*rstd*lng[tid+128] + lnb[tid+128]; orow[tid+128] = fmaxf(y1, 0.f);
  float y2 = d2*rstd*lng[tid+256] + lnb[tid+256]; orow[tid+256] = fmaxf(y2, 0.f);
  float y3 = d3*rstd*lng[tid+384] + lnb[tid+384]; orow[tid+384] = fmaxf(y3, 0.f);
}

// ---------------- final MLP ----------------
__global__ __launch_bounds__(128) void k_mlp(
  const float* __restrict__ w, const float* __restrict__ bptr, float* __restrict__ pred)
{
  __shared__ float s_red[4];
  int bI = blockIdx.x, tid = threadIdx.x;
  const float* xd = g_feat + (size_t)g_idd[bI]*512;
  const float* xc = g_feat + (size_t)g_idc[bI]*512;
  float s = 0.f;
  for (int j = tid; j < 512; j += 128) s += xd[j]*w[j] + xc[j]*w[512+j];
  s = warpSum(s);
  if ((tid & 31) == 0) s_red[tid>>5] = s;
  __syncthreads();
  if (tid == 0) pred[bI] = s_red[0]+s_red[1]+s_red[2]+s_red[3] + bptr[0];
}

// ---------------- host ----------------
static void launch_gemm(const float* A, const float* B, const float* bias, float* C,
                        int M, int K, int Nn)
{
  dim3 grid((Nn + BN - 1)/BN, (M + BM - 1)/BM);
  k_gemm_mma<<<grid, 256, SMEM_TOTAL_GEMM>>>(A, B, bias, C, M, K, Nn);
}

extern "C" void kernel_launch(void* const* d_in, const int* in_sizes, int n_in,
                              void* d_out, int out_size)
{
  static bool init_done = false;
  static cudaStream_t s2 = nullptr;
  static cudaEvent_t evA = nullptr, evB = nullptr;
  if (!init_done){
    cudaFuncSetAttribute(k_gemm_mma, cudaFuncAttributeMaxDynamicSharedMemorySize,
                         SMEM_TOTAL_GEMM);
    cudaStreamCreateWithFlags(&s2, cudaStreamNonBlocking);
    cudaEventCreateWithFlags(&evA, cudaEventDisableTiming);
    cudaEventCreateWithFlags(&evB, cudaEventDisableTiming);
    init_done = true;
  }

  bool used[64];
  for (int i = 0; i < 64; i++) used[i] = false;
  auto find = [&](int sz) -> int {
    for (int i = 0; i < n_in; i++)
      if (!used[i] && in_sizes[i] == sz){ used[i] = true; return i; }
    return -1;
  };
  int i_drug = find(250000),  i_cell = find(250000), i_gene = find(81000000);
  int i_ei   = find(400000),  i_ea   = find(200000);
  int i_idd  = find(8192),    i_idc  = find(8192);
  int i_Wd   = find(128000),  i_Wc   = find(128000), i_Wg = find(2304000);
  int i_bd   = find(256),     i_bc   = find(256),    i_bg = find(256);
  int i_l0lin = find(131072), i_l1lin = find(262144);
  int i_l0asrc=find(512), i_l0adst=find(512), i_l0ledge=find(512), i_l0aedge=find(512);
  int i_l0bias=find(512), i_l0lng=find(512),  i_l0lnb=find(512);
  int i_l1asrc=find(512), i_l1adst=find(512), i_l1ledge=find(512), i_l1aedge=find(512);
  int i_l1bias=find(512), i_l1lng=find(512),  i_l1lnb=find(512);
  int i_mw = find(1024), i_mb = find(1);
  if (i_gene < 0 || i_ei < 0 || i_mw < 0 || i_mb < 0){
    cudaMemsetAsync(d_out, 0, (size_t)out_size * sizeof(float));
    return;
  }

  const float* drug = (const float*)d_in[i_drug];
  const float* cell = (const float*)d_in[i_cell];
  const float* gene = (const float*)d_in[i_gene];
  const void*  ei   = d_in[i_ei];
  const float* ea   = (const float*)d_in[i_ea];
  const void*  idd  = d_in[i_idd];
  const void*  idc  = d_in[i_idc];
  const float* Wd = (const float*)d_in[i_Wd]; const float* bd = (const float*)d_in[i_bd];
  const float* Wc = (const float*)d_in[i_Wc]; const float* bc = (const float*)d_in[i_bc];
  const float* Wg = (const float*)d_in[i_Wg]; const float* bg = (const float*)d_in[i_bg];
  const float* l0lin = (const float*)d_in[i_l0lin];
  const float* l0asrc = (const float*)d_in[i_l0asrc]; const float* l0adst = (const float*)d_in[i_l0adst];
  const float* l0ledge = (const float*)d_in[i_l0ledge]; const float* l0aedge = (const float*)d_in[i_l0aedge];
  const float* l0bias = (const float*)d_in[i_l0bias];
  const float* l0lng = (const float*)d_in[i_l0lng]; const float* l0lnb = (const float*)d_in[i_l0lnb];
  const float* l1lin = (const float*)d_in[i_l1lin];
  const float* l1asrc = (const float*)d_in[i_l1asrc]; const float* l1adst = (const float*)d_in[i_l1adst];
  const float* l1ledge = (const float*)d_in[i_l1ledge]; const float* l1aedge = (const float*)d_in[i_l1aedge];
  const float* l1bias = (const float*)d_in[i_l1bias];
  const float* l1lng = (const float*)d_in[i_l1lng]; const float* l1lnb = (const float*)d_in[i_l1lnb];
  const float* mw = (const float*)d_in[i_mw]; const float* mb = (const float*)d_in[i_mb];

  float* pred = (float*)d_out;
  float* att  = pred + (out_size - (size_t)NN*NN);

  float *x0, *xh, *feat;
  cudaGetSymbolAddress((void**)&x0,   g_x0);
  cudaGetSymbolAddress((void**)&xh,   g_xh);
  cudaGetSymbolAddress((void**)&feat, g_feat);

  // ---- fork side stream: memset + graph preprocessing overlap the GEMMs ----
  cudaEventRecord(evA, 0);
  cudaStreamWaitEvent(s2, evA, 0);

  cudaMemsetAsync(d_out, 0, (size_t)out_size * sizeof(float), s2);   // 1
  k_zero<<<(NN+255)/256, 256, 0, s2>>>();                             // 2
  k_detect<<<(EREAL+255)/256, 256, 0, s2>>>((const long long*)ei);    // 3
  k_cvt_edges_deg<<<(EREAL+255)/256, 256, 0, s2>>>(ei, ea);           // 4

  // main stream: the heavy GEMMs (gene lands in the ncu-profiled slot)
  launch_gemm(gene, Wg, bg, x0 + 1000*256, 9000, 9000, 256);          // 5 <- profiled
  launch_gemm(drug, Wd, bd, x0,            500,  500,  256);
  launch_gemm(cell, Wc, bc, x0 + 500*256,  500,  500,  256);
  launch_gemm(x0, l0lin, nullptr, xh, NN, 256, 512);   // layer-0 lin (needs x0 only)

  // side stream: rest of preprocessing
  k_cvt_idx<<<(BBATCH+255)/256, 256, 0, s2>>>(idd, idc);
  k_loopattr<<<(NN+255)/256, 256, 0, s2>>>();
  k_scan<<<1, 1024, 0, s2>>>();
  k_scatter_all<<<(EREAL+NN+255)/256, 256, 0, s2>>>(ea);
  k_winner<<<NN, 32, 0, s2>>>();
  cudaEventRecord(evB, s2);

  // main continues: attention prep (independent of graph structure)
  k_ke<<<1, 128>>>(l0ledge, l0aedge);
  k_al<<<NN, 128>>>(xh, l0asrc, l0adst);

  // join: k_gat needs CSR + winner flags + zeroed att
  cudaStreamWaitEvent(0, evB, 0);
  k_gat<<<NN, 128>>>(xh, l0bias, l0lng, l0lnb, feat, att, 0);

  // GAT layer 1
  launch_gemm(feat, l1lin, nullptr, xh, NN, 512, 512);
  k_ke<<<1, 128>>>(l1ledge, l1aedge);
  k_al<<<NN, 128>>>(xh, l1asrc, l1adst);
  k_gat<<<NN, 128>>>(xh, l1bias, l1lng, l1lnb, feat, att, 1);

  k_mlp<<<8192, 128>>>(mw, mb, pred);
}

// round 10
// speedup vs baseline: 1.8874x; 1.0601x over previous
#include <cuda_runtime.h>
#include <cuda_bf16.h>
#include <math.h>
#include <float.h>
#include <stdint.h>

#define NN      10000
#define EREAL   200000
#define E2TOT   210000
#define BBATCH  8192

// ---------------- device scratch ----------------
__device__ float g_x0[NN*256];
__device__ float g_xh[NN*512];
__device__ float g_feat[NN*512];
__device__ float g_alsrc[NN*4];
__device__ float g_aldst[NN*4];
__device__ int   g_cnt[NN];
__device__ float g_attrsum[NN];
__device__ float g_loop[NN];
__device__ int   g_ptr[NN+1];
__device__ int   g_cur[NN];
__device__ int   g_csrc[E2TOT];
__device__ float g_cea[E2TOT];
__device__ int   g_corig[E2TOT];
__device__ unsigned char g_cwin[E2TOT];
__device__ float g_ke[4];
__device__ int   g_f64;
__device__ int   g_src[EREAL];
__device__ int   g_dst[EREAL];
__device__ int   g_idd[BBATCH];
__device__ int   g_idc[BBATCH];

// ---------------- helpers ----------------
__device__ __forceinline__ float warpSum(float v){
  #pragma unroll
  for (int o=16;o;o>>=1) v += __shfl_down_sync(0xffffffffu, v, o);
  return v;
}
__device__ __forceinline__ float warpMax(float v){
  #pragma unroll
  for (int o=16;o;o>>=1) v = fmaxf(v, __shfl_down_sync(0xffffffffu, v, o));
  return v;
}

// ---------------- preprocessing ----------------
__global__ void k_zero()
{
  int i = blockIdx.x*blockDim.x + threadIdx.x;
  if (i < NN){ g_cnt[i]=0; g_attrsum[i]=0.f; }
  if (i == 0) g_f64 = 1;
}

__global__ void k_detect(const long long* __restrict__ ei)
{
  int i = blockIdx.x*blockDim.x + threadIdx.x;
  if (i < EREAL){
    long long v = ei[i];
    if (v < 0 || v >= NN) g_f64 = 0;
  }
}

__global__ void k_cvt_edges_deg(const void* __restrict__ ei, const float* __restrict__ ea)
{
  int e = blockIdx.x*blockDim.x + threadIdx.x;
  if (e < EREAL){
    int s, d;
    if (g_f64){
      const long long* p = (const long long*)ei;
      s = (int)p[e]; d = (int)p[EREAL + e];
    } else {
      const int* p = (const int*)ei;
      s = p[e]; d = p[EREAL + e];
    }
    g_src[e] = s; g_dst[e] = d;
    atomicAdd(&g_cnt[d], 1);
    atomicAdd(&g_attrsum[d], ea[e]);
  }
}

__global__ void k_cvt_idx(const void* __restrict__ idd, const void* __restrict__ idc)
{
  int i = blockIdx.x*blockDim.x + threadIdx.x;
  if (i < BBATCH){
    if (g_f64){
      g_idd[i] = (int)((const long long*)idd)[i];
      g_idc[i] = (int)((const long long*)idc)[i];
    } else {
      g_idd[i] = ((const int*)idd)[i];
      g_idc[i] = ((const int*)idc)[i];
    }
  }
}

__global__ void k_loopattr()
{
  int i = blockIdx.x*blockDim.x + threadIdx.x;
  if (i < NN){
    float c = (float)g_cnt[i];
    g_loop[i] = g_attrsum[i] / fmaxf(c, 1.0f);
  }
}

__global__ void k_scan()
{
  __shared__ int s[1024];
  int tid = threadIdx.x;
  if (tid == 0) g_ptr[0] = 0;
  int offset = 0;
  for (int base = 0; base < NN; base += 1024){
    int i = base + tid;
    int v = (i < NN) ? (g_cnt[i] + 1) : 0;
    s[tid] = v; __syncthreads();
    for (int d = 1; d < 1024; d <<= 1){
      int t = (tid >= d) ? s[tid - d] : 0;
      __syncthreads();
      s[tid] += t;
      __syncthreads();
    }
    if (i < NN){
      g_ptr[i+1] = offset + s[tid];
      g_cur[i]   = offset + s[tid] - v;
    }
    int tot = s[1023];
    __syncthreads();
    offset += tot;
  }
}

__global__ void k_scatter_all(const float* __restrict__ ea)
{
  int idx = blockIdx.x*blockDim.x + threadIdx.x;
  if (idx < EREAL){
    int sI = g_src[idx], d = g_dst[idx];
    int pos = atomicAdd(&g_cur[d], 1);
    g_csrc[pos] = sI; g_cea[pos] = ea[idx]; g_corig[pos] = idx;
  } else if (idx < EREAL + NN){
    int n = idx - EREAL;
    int pos = atomicAdd(&g_cur[n], 1);
    g_csrc[pos] = n; g_cea[pos] = g_loop[n]; g_corig[pos] = EREAL + n;
  }
}

__global__ void k_winner()
{
  __shared__ int s_s[512], s_o[512];
  int n = blockIdx.x; int lane = threadIdx.x;
  int b = g_ptr[n], e = g_ptr[n+1];
  int len = e - b;
  if (len <= 512){
    for (int i = lane; i < len; i += 32){ s_s[i] = g_csrc[b+i]; s_o[i] = g_corig[b+i]; }
    __syncwarp();
    for (int i = lane; i < len; i += 32){
      int sI = s_s[i], o = s_o[i];
      unsigned char w = 1;
      for (int j = 0; j < len; j++)
        if (s_s[j] == sI && s_o[j] > o){ w = 0; break; }
      g_cwin[b+i] = w;
    }
  } else {
    for (int i = b + lane; i < e; i += 32){
      int sI = g_csrc[i]; int o = g_corig[i];
      unsigned char w = 1;
      for (int j = b; j < e; j++)
        if (g_csrc[j] == sI && g_corig[j] > o){ w = 0; break; }
      g_cwin[i] = w;
    }
  }
}

// ================= bf16 split-precision tensor-core GEMM =================
// C[M,Nn] = A[M,K] @ B[Nn,K]^T (+bias); fp32 in/out.
// x = hi + lo; C = Ah*Bh + Ah*Bl + Al*Bh.
// 512 threads (16 warps, 4x4 warp grid, warp tile 32x32), double-buffered smem.
#define BM 128
#define BN 128
#define BK 32
#define LDA 40                      // bf16 per row (80B)
#define ASZ (BM*LDA/2)              // u32 words per plane (2560)
#define STAGE_U32 (4*ASZ)
#define STAGE_BYTES (STAGE_U32*4)   // 40960
#define SMEM_TOTAL_GEMM (2*STAGE_BYTES)  // 81920
#define GT 512                      // threads per CTA

__device__ __forceinline__ void mma_bf16(
  float& c0, float& c1, float& c2, float& c3,
  uint32_t a0, uint32_t a1, uint32_t a2, uint32_t a3,
  uint32_t b0, uint32_t b1)
{
  asm volatile(
    "mma.sync.aligned.m16n8k16.row.col.f32.bf16.bf16.f32 "
    "{%0,%1,%2,%3}, {%4,%5,%6,%7}, {%8,%9}, {%0,%1,%2,%3};"
    : "+f"(c0), "+f"(c1), "+f"(c2), "+f"(c3)
    : "r"(a0), "r"(a1), "r"(a2), "r"(a3), "r"(b0), "r"(b1));
}

#define LDSM4(d0,d1,d2,d3,addr) \
  asm volatile("ldmatrix.sync.aligned.m8n8.x4.shared.b16 {%0,%1,%2,%3}, [%4];" \
    : "=r"(d0),"=r"(d1),"=r"(d2),"=r"(d3) : "r"(addr))

__device__ __forceinline__ uint32_t pack_hi(float x, float y){
  __nv_bfloat162 h = __floats2bfloat162_rn(x, y);
  return *reinterpret_cast<uint32_t*>(&h);
}
__device__ __forceinline__ uint32_t pack_lo(float x, float y){
  float hx = __bfloat162float(__float2bfloat16(x));
  float hy = __bfloat162float(__float2bfloat16(y));
  __nv_bfloat162 l = __floats2bfloat162_rn(x - hx, y - hy);
  return *reinterpret_cast<uint32_t*>(&l);
}

__global__ __launch_bounds__(GT, 1) void k_gemm_mma(
  const float* __restrict__ A, const float* __restrict__ B,
  const float* __restrict__ bias, float* __restrict__ C,
  int M, int K, int Nn)
{
  extern __shared__ __align__(16) uint32_t sdy[];   // [stage][Ah|Al|Bh|Bl]

  int tid = threadIdx.x;
  int lane = tid & 31, wid = tid >> 5;
  int gid = lane >> 2, tig = lane & 3;
  int mbase = (wid & 3) * 32;       // 4 warp-rows
  int nbase = (wid >> 2) * 32;      // 4 warp-cols
  int bm = blockIdx.y * BM, bn = blockIdx.x * BN;

  // ldmatrix byte-offsets relative to plane start
  int r8 = lane & 7, mat = lane >> 3;
  uint32_t smbase = (uint32_t)__cvta_generic_to_shared(sdy);
  uint32_t aoff[2], boff[2];
  #pragma unroll
  for (int mt = 0; mt < 2; mt++){
    int arow = mbase + mt*16 + (mat & 1)*8 + r8;
    aoff[mt] = (uint32_t)((arow*LDA + (mat >> 1)*8) * 2);
  }
  #pragma unroll
  for (int p = 0; p < 2; p++){
    int brow = nbase + p*16 + (mat >> 1)*8 + r8;
    boff[p] = (uint32_t)((brow*LDA + (mat & 1)*8) * 2);
  }

  float acc[2][4][4];
  #pragma unroll
  for (int i=0;i<2;i++)
    #pragma unroll
    for (int j=0;j<4;j++)
      #pragma unroll
      for (int q=0;q<4;q++) acc[i][j][q] = 0.f;

  float4 ra[2], rb[2];
  int tiles = (K + BK - 1) / BK;

  auto loadG = [&](const float* __restrict__ P, int rows, int rowbase, int k0, float4* r){
    #pragma unroll
    for (int i = 0; i < 2; i++){
      int f = tid + i*GT;
      int rr = f >> 3, cc = (f & 7) << 2;
      int gk = k0 + cc;
      float4 v = make_float4(0.f,0.f,0.f,0.f);
      int grow = rowbase + rr;
      if (grow < rows){
        const float* base = P + (size_t)grow*K + gk;
        if (gk + 3 < K) v = *reinterpret_cast<const float4*>(base);
        else {
          float t[4];
          #pragma unroll
          for (int u=0;u<4;u++) t[u] = (gk+u < K) ? base[u] : 0.f;
          v = make_float4(t[0],t[1],t[2],t[3]);
        }
      }
      r[i] = v;
    }
  };

  auto storeS = [&](int stage){
    uint32_t* Ah = sdy + stage*STAGE_U32;
    uint32_t* Al = Ah + ASZ;
    uint32_t* Bh = Al + ASZ;
    uint32_t* Bl = Bh + ASZ;
    #pragma unroll
    for (int i = 0; i < 2; i++){
      int f = tid + i*GT;
      int rr = f >> 3, cc = (f & 7) << 2;
      int idx = (rr*LDA + cc) >> 1;
      float4 v = ra[i];
      Ah[idx]   = pack_hi(v.x, v.y);
      Ah[idx+1] = pack_hi(v.z, v.w);
      Al[idx]   = pack_lo(v.x, v.y);
      Al[idx+1] = pack_lo(v.z, v.w);
      float4 w = rb[i];
      Bh[idx]   = pack_hi(w.x, w.y);
      Bh[idx+1] = pack_hi(w.z, w.w);
      Bl[idx]   = pack_lo(w.x, w.y);
      Bl[idx+1] = pack_lo(w.z, w.w);
    }
  };

  loadG(A, M, bm, 0, ra);
  loadG(B, Nn, bn, 0, rb);
  storeS(0);
  __syncthreads();

  for (int t = 0; t < tiles; t++){
    bool more = (t + 1 < tiles);
    if (more){
      loadG(A, M, bm, (t+1)*BK, ra);
      loadG(B, Nn, bn, (t+1)*BK, rb);
    }
    uint32_t stg = smbase + (uint32_t)((t & 1) * STAGE_BYTES);
    uint32_t aP0 = stg, aP1 = stg + ASZ*4;
    uint32_t bP0 = stg + 2*ASZ*4, bP1 = stg + 3*ASZ*4;
    #pragma unroll
    for (int ks = 0; ks < BK; ks += 16){
      uint32_t ah[2][4], al[2][4], bh[2][4], bl[2][4];
      #pragma unroll
      for (int mt = 0; mt < 2; mt++){
        LDSM4(ah[mt][0], ah[mt][1], ah[mt][2], ah[mt][3], aP0 + aoff[mt] + ks*2);
        LDSM4(al[mt][0], al[mt][1], al[mt][2], al[mt][3], aP1 + aoff[mt] + ks*2);
      }
      // bh[p] holds fragments for nt = 2p (regs 0,1) and nt = 2p+1 (regs 2,3)
      #pragma unroll
      for (int p = 0; p < 2; p++){
        LDSM4(bh[p][0], bh[p][1], bh[p][2], bh[p][3], bP0 + boff[p] + ks*2);
        LDSM4(bl[p][0], bl[p][1], bl[p][2], bl[p][3], bP1 + boff[p] + ks*2);
      }
      #pragma unroll
      for (int mt = 0; mt < 2; mt++)
        #pragma unroll
        for (int nt = 0; nt < 4; nt++){
          float* c = acc[mt][nt];
          uint32_t b0 = bh[nt>>1][(nt&1)*2], b1 = bh[nt>>1][(nt&1)*2+1];
          uint32_t c0 = bl[nt>>1][(nt&1)*2], c1 = bl[nt>>1][(nt&1)*2+1];
          mma_bf16(c[0],c[1],c[2],c[3], ah[mt][0],ah[mt][1],ah[mt][2],ah[mt][3], b0,b1);
          mma_bf16(c[0],c[1],c[2],c[3], ah[mt][0],ah[mt][1],ah[mt][2],ah[mt][3], c0,c1);
          mma_bf16(c[0],c[1],c[2],c[3], al[mt][0],al[mt][1],al[mt][2],al[mt][3], b0,b1);
        }
    }
    if (more) storeS((t+1) & 1);
    __syncthreads();
  }

  #pragma unroll
  for (int mt = 0; mt < 2; mt++){
    int row0 = bm + mbase + mt*16 + gid;
    #pragma unroll
    for (int nt = 0; nt < 4; nt++){
      int col0 = bn + nbase + nt*8 + tig*2;
      float* c = acc[mt][nt];
      float b0 = bias ? bias[col0] : 0.f;
      float b1 = bias ? bias[col0+1] : 0.f;
      if (row0 < M){
        float2 v = make_float2(c[0] + b0, c[1] + b1);
        *reinterpret_cast<float2*>(C + (size_t)row0*Nn + col0) = v;
      }
      if (row0 + 8 < M){
        float2 v = make_float2(c[2] + b0, c[3] + b1);
        *reinterpret_cast<float2*>(C + (size_t)(row0+8)*Nn + col0) = v;
      }
    }
  }
}

// ---------------- per-layer small kernels ----------------
__global__ void k_ke(const float* __restrict__ ledge, const float* __restrict__ aedge)
{
  int w = threadIdx.x >> 5, lane = threadIdx.x & 31;
  float s = 0.f;
  for (int c = lane; c < 128; c += 32) s += ledge[w*128+c]*aedge[w*128+c];
  s = warpSum(s);
  if (lane == 0) g_ke[w] = s;
}

__global__ void k_al(const float* __restrict__ xh,
                     const float* __restrict__ asrc, const float* __restrict__ adst)
{
  int n = blockIdx.x; int w = threadIdx.x >> 5, lane = threadIdx.x & 31;
  const float* row = xh + (size_t)n*512 + w*128;
  float s1 = 0.f, s2 = 0.f;
  for (int c = lane; c < 128; c += 32){
    float v = row[c];
    s1 += v*asrc[w*128+c];
    s2 += v*adst[w*128+c];
  }
  s1 = warpSum(s1); s2 = warpSum(s2);
  if (lane == 0){ g_alsrc[n*4+w] = s1; g_aldst[n*4+w] = s2; }
}

// ---------------- GAT node kernel ----------------
#define CHUNK 512
__global__ __launch_bounds__(128) void k_gat(
  const float* __restrict__ xh,
  const float* __restrict__ bias,
  const float* __restrict__ lng, const float* __restrict__ lnb,
  float* __restrict__ xout, float* __restrict__ att, int layer)
{
  __shared__ float s_alpha[CHUNK*4];
  __shared__ int   s_src[CHUNK];
  __shared__ float s_red[16];
  int n = blockIdx.x, tid = threadIdx.x;
  int warp = tid >> 5, lane = tid & 31;
  int b = g_ptr[n], e = g_ptr[n+1];

  float ad0 = g_aldst[n*4+0], ad1 = g_aldst[n*4+1], ad2 = g_aldst[n*4+2], ad3 = g_aldst[n*4+3];
  float ke0 = g_ke[0], ke1 = g_ke[1], ke2 = g_ke[2], ke3 = g_ke[3];

  float mx0=-FLT_MAX, mx1=-FLT_MAX, mx2=-FLT_MAX, mx3=-FLT_MAX;
  for (int i = b + tid; i < e; i += 128){
    int sI = g_csrc[i]; float ea = g_cea[i];
    float l0 = g_alsrc[sI*4+0]+ad0+ea*ke0; l0 = l0>0.f? l0 : 0.2f*l0;
    float l1 = g_alsrc[sI*4+1]+ad1+ea*ke1; l1 = l1>0.f? l1 : 0.2f*l1;
    float l2 = g_alsrc[sI*4+2]+ad2+ea*ke2; l2 = l2>0.f? l2 : 0.2f*l2;
    float l3 = g_alsrc[sI*4+3]+ad3+ea*ke3; l3 = l3>0.f? l3 : 0.2f*l3;
    mx0=fmaxf(mx0,l0); mx1=fmaxf(mx1,l1); mx2=fmaxf(mx2,l2); mx3=fmaxf(mx3,l3);
  }
  mx0=warpMax(mx0); mx1=warpMax(mx1); mx2=warpMax(mx2); mx3=warpMax(mx3);
  if (lane==0){ s_red[warp*4+0]=mx0; s_red[warp*4+1]=mx1; s_red[warp*4+2]=mx2; s_red[warp*4+3]=mx3; }
  __syncthreads();
  float bm0 = fmaxf(fmaxf(s_red[0],s_red[4]),  fmaxf(s_red[8], s_red[12]));
  float bm1 = fmaxf(fmaxf(s_red[1],s_red[5]),  fmaxf(s_red[9], s_red[13]));
  float bm2 = fmaxf(fmaxf(s_red[2],s_red[6]),  fmaxf(s_red[10],s_red[14]));
  float bm3 = fmaxf(fmaxf(s_red[3],s_red[7]),  fmaxf(s_red[11],s_red[15]));
  __syncthreads();

  float se0=0.f, se1=0.f, se2=0.f, se3=0.f;
  for (int i = b + tid; i < e; i += 128){
    int sI = g_csrc[i]; float ea = g_cea[i];
    float l0 = g_alsrc[sI*4+0]+ad0+ea*ke0; l0 = l0>0.f? l0 : 0.2f*l0;
    float l1 = g_alsrc[sI*4+1]+ad1+ea*ke1; l1 = l1>0.f? l1 : 0.2f*l1;
    float l2 = g_alsrc[sI*4+2]+ad2+ea*ke2; l2 = l2>0.f? l2 : 0.2f*l2;
    float l3 = g_alsrc[sI*4+3]+ad3+ea*ke3; l3 = l3>0.f? l3 : 0.2f*l3;
    se0 += expf(l0-bm0); se1 += expf(l1-bm1); se2 += expf(l2-bm2); se3 += expf(l3-bm3);
  }
  se0=warpSum(se0); se1=warpSum(se1); se2=warpSum(se2); se3=warpSum(se3);
  if (lane==0){ s_red[warp*4+0]=se0; s_red[warp*4+1]=se1; s_red[warp*4+2]=se2; s_red[warp*4+3]=se3; }
  __syncthreads();
  float inv0 = 1.f/((s_red[0]+s_red[4]+s_red[8] +s_red[12])+1e-16f);
  float inv1 = 1.f/((s_red[1]+s_red[5]+s_red[9] +s_red[13])+1e-16f);
  float inv2 = 1.f/((s_red[2]+s_red[6]+s_red[10]+s_red[14])+1e-16f);
  float inv3 = 1.f/((s_red[3]+s_red[7]+s_red[11]+s_red[15])+1e-16f);
  __syncthreads();

  float acc0=0.f, acc1=0.f, acc2=0.f, acc3=0.f;
  for (int c0 = b; c0 < e; c0 += CHUNK){
    int cl = min(CHUNK, e - c0);
    for (int i = tid; i < cl; i += 128){
      int eI = c0 + i;
      int sI = g_csrc[eI]; float ea = g_cea[eI];
      float l0 = g_alsrc[sI*4+0]+ad0+ea*ke0; l0 = l0>0.f? l0 : 0.2f*l0;
      float l1 = g_alsrc[sI*4+1]+ad1+ea*ke1; l1 = l1>0.f? l1 : 0.2f*l1;
      float l2 = g_alsrc[sI*4+2]+ad2+ea*ke2; l2 = l2>0.f? l2 : 0.2f*l2;
      float l3 = g_alsrc[sI*4+3]+ad3+ea*ke3; l3 = l3>0.f? l3 : 0.2f*l3;
      float a0 = expf(l0-bm0)*inv0, a1 = expf(l1-bm1)*inv1;
      float a2 = expf(l2-bm2)*inv2, a3 = expf(l3-bm3)*inv3;
      s_alpha[i*4+0]=a0; s_alpha[i*4+1]=a1; s_alpha[i*4+2]=a2; s_alpha[i*4+3]=a3;
      s_src[i] = sI;
      if (g_cwin[eI]){
        float v = (a0+a1+a2+a3)*0.25f;
        size_t ai = (size_t)sI*NN + n;
        if (layer == 0) att[ai] = v; else att[ai] += v;
      }
    }
    __syncthreads();
    for (int i = 0; i < cl; i++){
      const float* row = xh + (size_t)s_src[i]*512;
      float a0=s_alpha[i*4+0], a1=s_alpha[i*4+1], a2=s_alpha[i*4+2], a3=s_alpha[i*4+3];
      acc0 += a0*row[tid];
      acc1 += a1*row[tid+128];
      acc2 += a2*row[tid+256];
      acc3 += a3*row[tid+384];
    }
    __syncthreads();
  }

  acc0 += bias[tid]; acc1 += bias[tid+128]; acc2 += bias[tid+256]; acc3 += bias[tid+384];
  float ps = acc0+acc1+acc2+acc3;
  ps = warpSum(ps);
  if (lane==0) s_red[warp]=ps;
  __syncthreads();
  float mu = (s_red[0]+s_red[1]+s_red[2]+s_red[3]) * (1.f/512.f);
  __syncthreads();
  float d0=acc0-mu, d1=acc1-mu, d2=acc2-mu, d3=acc3-mu;
  float pv = d0*d0+d1*d1+d2*d2+d3*d3;
  pv = warpSum(pv);
  if (lane==0) s_red[warp]=pv;
  __syncthreads();
  float var = (s_red[0]+s_red[1]+s_red[2]+s_red[3]) * (1.f/512.f);
  float rstd = rsqrtf(var + 1e-5f);
  float* orow = xout + (size_t)n*512;
  float y0 = d0*rstd*lng[tid]     + lnb[tid];     orow[tid]     = fmaxf(y0, 0.f);
  float y1 = d1*rstd*lng[tid+128] + lnb[tid+128]; orow[tid+128] = fmaxf(y1, 0.f);
  float y2 = d2*rstd*lng[tid+256] + lnb[tid+256]; orow[tid+256] = fmaxf(y2, 0.f);
  float y3 = d3*rstd*lng[tid+384] + lnb[tid+384]; orow[tid+384] = fmaxf(y3, 0.f);
}

// ---------------- final MLP ----------------
__global__ __launch_bounds__(128) void k_mlp(
  const float* __restrict__ w, const float* __restrict__ bptr, float* __restrict__ pred)
{
  __shared__ float s_red[4];
  int bI = blockIdx.x, tid = threadIdx.x;
  const float* xd = g_feat + (size_t)g_idd[bI]*512;
  const float* xc = g_feat + (size_t)g_idc[bI]*512;
  float s = 0.f;
  for (int j = tid; j < 512; j += 128) s += xd[j]*w[j] + xc[j]*w[512+j];
  s = warpSum(s);
  if ((tid & 31) == 0) s_red[tid>>5] = s;
  __syncthreads();
  if (tid == 0) pred[bI] = s_red[0]+s_red[1]+s_red[2]+s_red[3] + bptr[0];
}

// ---------------- host ----------------
static void launch_gemm_s(const float* A, const float* B, const float* bias, float* C,
                          int M, int K, int Nn, cudaStream_t st)
{
  dim3 grid((Nn + BN - 1)/BN, (M + BM - 1)/BM);
  k_gemm_mma<<<grid, GT, SMEM_TOTAL_GEMM, st>>>(A, B, bias, C, M, K, Nn);
}

extern "C" void kernel_launch(void* const* d_in, const int* in_sizes, int n_in,
                              void* d_out, int out_size)
{
  static bool init_done = false;
  static cudaStream_t s2 = nullptr, s3 = nullptr;
  static cudaEvent_t evA = nullptr, evB = nullptr, evC = nullptr;
  if (!init_done){
    cudaFuncSetAttribute(k_gemm_mma, cudaFuncAttributeMaxDynamicSharedMemorySize,
                         SMEM_TOTAL_GEMM);
    cudaStreamCreateWithFlags(&s2, cudaStreamNonBlocking);
    cudaStreamCreateWithFlags(&s3, cudaStreamNonBlocking);
    cudaEventCreateWithFlags(&evA, cudaEventDisableTiming);
    cudaEventCreateWithFlags(&evB, cudaEventDisableTiming);
    cudaEventCreateWithFlags(&evC, cudaEventDisableTiming);
    init_done = true;
  }

  bool used[64];
  for (int i = 0; i < 64; i++) used[i] = false;
  auto find = [&](int sz) -> int {
    for (int i = 0; i < n_in; i++)
      if (!used[i] && in_sizes[i] == sz){ used[i] = true; return i; }
    return -1;
  };
  int i_drug = find(250000),  i_cell = find(250000), i_gene = find(81000000);
  int i_ei   = find(400000),  i_ea   = find(200000);
  int i_idd  = find(8192),    i_idc  = find(8192);
  int i_Wd   = find(128000),  i_Wc   = find(128000), i_Wg = find(2304000);
  int i_bd   = find(256),     i_bc   = find(256),    i_bg = find(256);
  int i_l0lin = find(131072), i_l1lin = find(262144);
  int i_l0asrc=find(512), i_l0adst=find(512), i_l0ledge=find(512), i_l0aedge=find(512);
  int i_l0bias=find(512), i_l0lng=find(512),  i_l0lnb=find(512);
  int i_l1asrc=find(512), i_l1adst=find(512), i_l1ledge=find(512), i_l1aedge=find(512);
  int i_l1bias=find(512), i_l1lng=find(512),  i_l1lnb=find(512);
  int i_mw = find(1024), i_mb = find(1);
  if (i_gene < 0 || i_ei < 0 || i_mw < 0 || i_mb < 0){
    cudaMemsetAsync(d_out, 0, (size_t)out_size * sizeof(float));
    return;
  }

  const float* drug = (const float*)d_in[i_drug];
  const float* cell = (const float*)d_in[i_cell];
  const float* gene = (const float*)d_in[i_gene];
  const void*  ei   = d_in[i_ei];
  const float* ea   = (const float*)d_in[i_ea];
  const void*  idd  = d_in[i_idd];
  const void*  idc  = d_in[i_idc];
  const float* Wd = (const float*)d_in[i_Wd]; const float* bd = (const float*)d_in[i_bd];
  const float* Wc = (const float*)d_in[i_Wc]; const float* bc = (const float*)d_in[i_bc];
  const float* Wg = (const float*)d_in[i_Wg]; const float* bg = (const float*)d_in[i_bg];
  const float* l0lin = (const float*)d_in[i_l0lin];
  const float* l0asrc = (const float*)d_in[i_l0asrc]; const float* l0adst = (const float*)d_in[i_l0adst];
  const float* l0ledge = (const float*)d_in[i_l0ledge]; const float* l0aedge = (const float*)d_in[i_l0aedge];
  const float* l0bias = (const float*)d_in[i_l0bias];
  const float* l0lng = (const float*)d_in[i_l0lng]; const float* l0lnb = (const float*)d_in[i_l0lnb];
  const float* l1lin = (const float*)d_in[i_l1lin];
  const float* l1asrc = (const float*)d_in[i_l1asrc]; const float* l1adst = (const float*)d_in[i_l1adst];
  const float* l1ledge = (const float*)d_in[i_l1ledge]; const float* l1aedge = (const float*)d_in[i_l1aedge];
  const float* l1bias = (const float*)d_in[i_l1bias];
  const float* l1lng = (const float*)d_in[i_l1lng]; const float* l1lnb = (const float*)d_in[i_l1lnb];
  const float* mw = (const float*)d_in[i_mw]; const float* mb = (const float*)d_in[i_mb];

  float* pred = (float*)d_out;
  float* att  = pred + (out_size - (size_t)NN*NN);

  float *x0, *xh, *feat;
  cudaGetSymbolAddress((void**)&x0,   g_x0);
  cudaGetSymbolAddress((void**)&xh,   g_xh);
  cudaGetSymbolAddress((void**)&feat, g_feat);

  // fork: side streams overlap memset/preproc and small GEMMs with the gene GEMM
  cudaEventRecord(evA, 0);
  cudaStreamWaitEvent(s2, evA, 0);
  cudaStreamWaitEvent(s3, evA, 0);

  cudaMemsetAsync(d_out, 0, (size_t)out_size * sizeof(float), s2);   // 1
  k_zero<<<(NN+255)/256, 256, 0, s2>>>();                             // 2
  k_detect<<<(EREAL+255)/256, 256, 0, s2>>>((const long long*)ei);    // 3
  k_cvt_edges_deg<<<(EREAL+255)/256, 256, 0, s2>>>(ei, ea);           // 4

  // main stream: gene GEMM (ncu-profiled slot)
  launch_gemm_s(gene, Wg, bg, x0 + 1000*256, 9000, 9000, 256, 0);     // 5 <- profiled

  // s3: small projection GEMMs overlap gene
  launch_gemm_s(drug, Wd, bd, x0,            500, 500, 256, s3);
  launch_gemm_s(cell, Wc, bc, x0 + 500*256,  500, 500, 256, s3);
  cudaEventRecord(evC, s3);

  // s2: rest of graph preprocessing
  k_cvt_idx<<<(BBATCH+255)/256, 256, 0, s2>>>(idd, idc);
  k_loopattr<<<(NN+255)/256, 256, 0, s2>>>();
  k_scan<<<1, 1024, 0, s2>>>();
  k_scatter_all<<<(EREAL+NN+255)/256, 256, 0, s2>>>(ea);
  k_winner<<<NN, 32, 0, s2>>>();
  cudaEventRecord(evB, s2);

  // main: l0 lin needs full x0 (gene on main + drug/cell on s3)
  cudaStreamWaitEvent(0, evC, 0);
  launch_gemm_s(x0, l0lin, nullptr, xh, NN, 256, 512, 0);
  k_ke<<<1, 128>>>(l0ledge, l0aedge);
  k_al<<<NN, 128>>>(xh, l0asrc, l0adst);

  // join graph preprocessing before k_gat
  cudaStreamWaitEvent(0, evB, 0);
  k_gat<<<NN, 128>>>(xh, l0bias, l0lng, l0lnb, feat, att, 0);

  // GAT layer 1
  launch_gemm_s(feat, l1lin, nullptr, xh, NN, 512, 512, 0);
  k_ke<<<1, 128>>>(l1ledge, l1aedge);
  k_al<<<NN, 128>>>(xh, l1asrc, l1adst);
  k_gat<<<NN, 128>>>(xh, l1bias, l1lng, l1lnb, feat, att, 1);

  k_mlp<<<8192, 128>>>(mw, mb, pred);
}